// round 4
// baseline (speedup 1.0000x reference)
#include <cuda_runtime.h>
#include <cuda_bf16.h>
#include <cstdint>

#define HID 90
#define HP 96
#define NNODES 1024
#define BATCH 1024
#define TPB 512
#define ROWS 128
#define RSTRIDE 208          // bytes per smem matrix row — conflict-free ldmatrix

// ---------------- device globals (no allocation allowed) ----------------
__device__ float c1g[NNODES * HP];                       // per-node layer-1 bias
__device__ __align__(16) unsigned char Bimg[39936];      // W2^T bf16 hi (19968) + lo

// ---------------- smem layout ----------------
#define SM_A_HI 0
#define SM_A_LO 26624
#define SM_B_HI 53248
#define SM_B_LO 73216
#define SM_W1   93184
#define SM_BW   95872
#define SM_PAT  96640        // reused as 256-float partial buffer in phase 3
#define SM_IL   98688
#define SM_TOTAL 100736

__device__ __forceinline__ uint32_t smem_u32(const void* p) {
    uint32_t a;
    asm("{ .reg .u64 t; cvta.to.shared.u64 t, %1; cvt.u32.u64 %0, t; }"
        : "=r"(a) : "l"(p));
    return a;
}
__device__ __forceinline__ void ldsm_x4(uint32_t& r0, uint32_t& r1,
                                        uint32_t& r2, uint32_t& r3, uint32_t a) {
    asm volatile("ldmatrix.sync.aligned.m8n8.x4.shared.b16 {%0,%1,%2,%3}, [%4];"
                 : "=r"(r0), "=r"(r1), "=r"(r2), "=r"(r3) : "r"(a));
}
__device__ __forceinline__ void mma16816(float* c, uint32_t a0, uint32_t a1,
                                         uint32_t a2, uint32_t a3,
                                         uint32_t b0, uint32_t b1) {
    asm volatile(
        "mma.sync.aligned.m16n8k16.row.col.f32.bf16.bf16.f32 "
        "{%0,%1,%2,%3}, {%4,%5,%6,%7}, {%8,%9}, {%0,%1,%2,%3};"
        : "+f"(c[0]), "+f"(c[1]), "+f"(c[2]), "+f"(c[3])
        : "r"(a0), "r"(a1), "r"(a2), "r"(a3), "r"(b0), "r"(b1));
}
__device__ __forceinline__ unsigned long long pack2(float x, float y) {
    unsigned long long r;
    asm("mov.b64 %0, {%1, %2};" : "=l"(r) : "f"(x), "f"(y));
    return r;
}
__device__ __forceinline__ void unpack2(unsigned long long v, float& x, float& y) {
    asm("mov.b64 {%0, %1}, %2;" : "=f"(x), "=f"(y) : "l"(v));
}
__device__ __forceinline__ void ffma2(unsigned long long& c, unsigned long long a,
                                      unsigned long long b) {
    asm("fma.rn.f32x2 %0, %1, %2, %0;" : "+l"(c) : "l"(a), "l"(b));
}
__device__ __forceinline__ float elu(float v) {
    return v > 0.f ? v : (__expf(v) - 1.f);
}

// ---------------- merged prep kernel (c1 + W2^T bf16 split) -------------
__global__ void prep_kernel(const float* __restrict__ controls,
                            const float* __restrict__ W1,
                            const float* __restrict__ b1,
                            const int* __restrict__ control_list,
                            const float* __restrict__ W2) {
    int n = blockIdx.x;       // 1024
    int j = threadIdx.x;      // 96
    float v = 0.f;
    if (j < HID) {
        v = b1[j];
#pragma unroll
        for (int kk = 0; kk < 3; kk++) {
            int e = control_list[n * 3 + kk];
            v = fmaf(controls[n * 3 + kk], W1[e * HID + j], v);
        }
    }
    c1g[n * HP + j] = v;
    if (n < HP) {
        // Bimg row n (output col), element k=j: bf16 split of W2[k][n]
        float w = (n < HID && j < HID) ? W2[j * HID + n] : 0.f;
        __nv_bfloat16 h = __float2bfloat16(w);
        __nv_bfloat16 l = __float2bfloat16(w - __bfloat162float(h));
        uint32_t off = (uint32_t)n * RSTRIDE + (uint32_t)j * 2;
        *(__nv_bfloat16*)(Bimg + off) = h;
        *(__nv_bfloat16*)(Bimg + 19968 + off) = l;
    }
}

// ---------------- main kernel ----------------
__global__ void __launch_bounds__(TPB, 1)
lrf_main_kernel(const float* __restrict__ x,
                const float* __restrict__ W1,
                const float* __restrict__ b2,
                const float* __restrict__ W3,
                const float* __restrict__ b3,
                const int* __restrict__ inputs_list,
                float* __restrict__ out) {
    extern __shared__ char sm[];
    const uint32_t smb = smem_u32(sm);
    const int tid = threadIdx.x;
    const int wid = tid >> 5, lid = tid & 31;
    const int b  = blockIdx.x >> 3;
    const int n0 = (blockIdx.x & 7) * ROWS;

    // ---- stage B (hi+lo, 39936 B) ----
    {
        const uint4* src = (const uint4*)Bimg;
        uint4* dst = (uint4*)(sm + SM_B_HI);
        for (int i = tid; i < 39936 / 16; i += TPB) dst[i] = src[i];
    }
    // ---- stage W1 (zero-pad cols), fused [b2,W3] pairs ----
    for (int idx = tid; idx < 7 * HP; idx += TPB) {
        int e = idx / HP, j = idx - e * HP;
        ((float*)(sm + SM_W1))[idx] = (j < HID) ? W1[e * HID + j] : 0.f;
    }
    if (tid < HP) {
        float bb = (tid < HID) ? b2[tid] : 0.f;
        float ww = (tid < HID) ? W3[tid] : 0.f;
        ((float*)(sm + SM_BW))[tid * 2]     = bb;
        ((float*)(sm + SM_BW))[tid * 2 + 1] = ww;
    }
    // ---- stage patches + electrode indices ----
    if (tid < ROWS) {
        int n = n0 + tid;
        int pw = n & 31, ph = n >> 5;
        const float* xb = x + (size_t)b * 4096 + ph * 128 + pw * 2;
        float2 r0 = *reinterpret_cast<const float2*>(xb);
        float2 r1 = *reinterpret_cast<const float2*>(xb + 64);
        *reinterpret_cast<float4*>(sm + SM_PAT + tid * 16) =
            make_float4(r0.x, r0.y, r1.x, r1.y);
        *reinterpret_cast<int4*>(sm + SM_IL + tid * 16) =
            *reinterpret_cast<const int4*>(inputs_list + n * 4);
    }
    __syncthreads();

    // ---- phase 1: h1 = elu(c1 + patch·W1rows); bf16 hi/lo into A tiles ----
    const float* W1s = (const float*)(sm + SM_W1);
#pragma unroll
    for (int it = 0; it < 3; it++) {
        int item = it * TPB + tid;          // 128 rows x 12 col-groups
        int r = item / 12, jg = item - r * 12;
        int j0 = jg * 8;
        float4 pv = *reinterpret_cast<float4*>(sm + SM_PAT + r * 16);
        int4 ii = *reinterpret_cast<int4*>(sm + SM_IL + r * 16);
        const float* c1p = c1g + (n0 + r) * HP + j0;
        float4 cA = *reinterpret_cast<const float4*>(c1p);
        float4 cB = *reinterpret_cast<const float4*>(c1p + 4);
        unsigned long long a0 = pack2(cA.x, cA.y), a1 = pack2(cA.z, cA.w);
        unsigned long long a2 = pack2(cB.x, cB.y), a3 = pack2(cB.z, cB.w);
#define EACC(EIDX, P) { \
        const float4* wr = (const float4*)(W1s + (EIDX) * HP + j0); \
        float4 w0 = wr[0], w1 = wr[1]; \
        unsigned long long pp = pack2((P), (P)); \
        ffma2(a0, pp, pack2(w0.x, w0.y)); \
        ffma2(a1, pp, pack2(w0.z, w0.w)); \
        ffma2(a2, pp, pack2(w1.x, w1.y)); \
        ffma2(a3, pp, pack2(w1.z, w1.w)); }
        EACC(ii.x, pv.x) EACC(ii.y, pv.y) EACC(ii.z, pv.z) EACC(ii.w, pv.w)
#undef EACC
        float v[8];
        unpack2(a0, v[0], v[1]); unpack2(a1, v[2], v[3]);
        unpack2(a2, v[4], v[5]); unpack2(a3, v[6], v[7]);
        uint32_t hi[4], lo[4];
#pragma unroll
        for (int q = 0; q < 4; q++) {
            float a = elu(v[2 * q]), c = elu(v[2 * q + 1]);
            __nv_bfloat16 ha = __float2bfloat16(a), hc = __float2bfloat16(c);
            __nv_bfloat16 la = __float2bfloat16(a - __bfloat162float(ha));
            __nv_bfloat16 lc = __float2bfloat16(c - __bfloat162float(hc));
            hi[q] = (uint32_t)__bfloat16_as_ushort(ha)
                  | ((uint32_t)__bfloat16_as_ushort(hc) << 16);
            lo[q] = (uint32_t)__bfloat16_as_ushort(la)
                  | ((uint32_t)__bfloat16_as_ushort(lc) << 16);
        }
        uint32_t off = (uint32_t)r * RSTRIDE + (uint32_t)j0 * 2;
        *reinterpret_cast<uint4*>(sm + SM_A_HI + off) = make_uint4(hi[0], hi[1], hi[2], hi[3]);
        *reinterpret_cast<uint4*>(sm + SM_A_LO + off) = make_uint4(lo[0], lo[1], lo[2], lo[3]);
    }
    __syncthreads();

    // ---- phase 2: warp = m16 x n48; B_hi shared between A_hi & A_lo ----
    const int rowTile = wid >> 1;            // 0..7
    const int nHalf   = wid & 1;             // 0..1
    const int ncol0   = nHalf * 48;

    float acc[6][4];
#pragma unroll
    for (int nt = 0; nt < 6; nt++)
#pragma unroll
        for (int q = 0; q < 4; q++) acc[nt][q] = 0.f;

    const uint32_t aRow = (uint32_t)(rowTile * 16 + (lid & 7) + ((lid >> 3) & 1) * 8) * RSTRIDE
                        + (uint32_t)(lid >> 4) * 16;
    const uint32_t bRow = (uint32_t)(ncol0 + (lid & 7) + (lid >> 4) * 8) * RSTRIDE
                        + (uint32_t)((lid >> 3) & 1) * 16;
    const uint32_t aHi = smb + SM_A_HI + aRow, aLo = smb + SM_A_LO + aRow;
    const uint32_t bHi = smb + SM_B_HI + bRow, bLo = smb + SM_B_LO + bRow;

#pragma unroll
    for (int kk = 0; kk < 6; kk++) {
        uint32_t h0, h1, h2, h3, l0, l1, l2, l3;
        ldsm_x4(h0, h1, h2, h3, aHi + kk * 32);
        ldsm_x4(l0, l1, l2, l3, aLo + kk * 32);
#pragma unroll
        for (int nt2 = 0; nt2 < 3; nt2++) {
            uint32_t b0, b1, b2r, b3r;
            ldsm_x4(b0, b1, b2r, b3r, bHi + (uint32_t)nt2 * 16 * RSTRIDE + kk * 32);
            mma16816(acc[2 * nt2],     h0, h1, h2, h3, b0,  b1);
            mma16816(acc[2 * nt2 + 1], h0, h1, h2, h3, b2r, b3r);
            mma16816(acc[2 * nt2],     l0, l1, l2, l3, b0,  b1);
            mma16816(acc[2 * nt2 + 1], l0, l1, l2, l3, b2r, b3r);
        }
    }
#pragma unroll
    for (int kk = 0; kk < 6; kk++) {
        uint32_t h0, h1, h2, h3;
        ldsm_x4(h0, h1, h2, h3, aHi + kk * 32);
#pragma unroll
        for (int nt2 = 0; nt2 < 3; nt2++) {
            uint32_t b0, b1, b2r, b3r;
            ldsm_x4(b0, b1, b2r, b3r, bLo + (uint32_t)nt2 * 16 * RSTRIDE + kk * 32);
            mma16816(acc[2 * nt2],     h0, h1, h2, h3, b0,  b1);
            mma16816(acc[2 * nt2 + 1], h0, h1, h2, h3, b2r, b3r);
        }
    }

    // ---- phase 3: partial dot with W3, cross-warp combine via smem ----
    float part0 = 0.f, part1 = 0.f;
    const char* bwp = sm + SM_BW + (size_t)ncol0 * 8 + (size_t)(lid & 3) * 16;
#pragma unroll
    for (int nt = 0; nt < 6; nt++) {
        float4 bw = *reinterpret_cast<const float4*>(bwp + nt * 64);
        part0 = fmaf(elu(acc[nt][0] + bw.x), bw.y, part0);
        part0 = fmaf(elu(acc[nt][1] + bw.z), bw.w, part0);
        part1 = fmaf(elu(acc[nt][2] + bw.x), bw.y, part1);
        part1 = fmaf(elu(acc[nt][3] + bw.z), bw.w, part1);
    }
#pragma unroll
    for (int off = 1; off < 4; off <<= 1) {
        part0 += __shfl_xor_sync(0xffffffffu, part0, off);
        part1 += __shfl_xor_sync(0xffffffffu, part1, off);
    }
    __syncthreads();                        // A tiles / PAT no longer needed
    float* PART = (float*)(sm + SM_PAT);
    if ((lid & 3) == 0) {
        int r0 = rowTile * 16 + (lid >> 2);
        PART[nHalf * 128 + r0]     = part0;
        PART[nHalf * 128 + r0 + 8] = part1;
    }
    __syncthreads();
    if (tid < ROWS)
        out[(size_t)b * NNODES + n0 + tid] = PART[tid] + PART[128 + tid] + b3[0];
}

extern "C" void kernel_launch(void* const* d_in, const int* in_sizes, int n_in,
                              void* d_out, int out_size) {
    const float* x            = (const float*)d_in[0];
    const float* controls     = (const float*)d_in[1];
    const float* W1           = (const float*)d_in[2];
    const float* b1           = (const float*)d_in[3];
    const float* W2           = (const float*)d_in[4];
    const float* b2           = (const float*)d_in[5];
    const float* W3           = (const float*)d_in[6];
    const float* b3           = (const float*)d_in[7];
    const int*   inputs_list  = (const int*)d_in[8];
    const int*   control_list = (const int*)d_in[9];
    float* out = (float*)d_out;

    cudaFuncSetAttribute(lrf_main_kernel,
                         cudaFuncAttributeMaxDynamicSharedMemorySize, SM_TOTAL);

    prep_kernel<<<NNODES, HP>>>(controls, W1, b1, control_list, W2);
    lrf_main_kernel<<<BATCH * (NNODES / ROWS), TPB, SM_TOTAL>>>(
        x, W1, b2, W3, b3, inputs_list, out);
}

// round 5
// speedup vs baseline: 1.1873x; 1.1873x over previous
#include <cuda_runtime.h>
#include <cuda_bf16.h>
#include <cstdint>

#define HID 90
#define HP 96
#define NNODES 1024
#define BATCH 1024
#define TPB 256
#define ROWS 128
#define RS 400               // bytes per smem matrix row (100 fp32) — conflict-free ldmatrix

// ---------------- device globals (no allocation allowed) ----------------
__device__ float c1g[NNODES * HP];                   // per-node layer-1 bias
__device__ __align__(16) float Bimg[96 * 100];       // W2^T, tf32-rounded, n-major

// ---------------- smem layout ----------------
#define SM_A   0             // 128 x 400 B = 51200
#define SM_B   51200         // 96 x 400 B  = 38400
#define SM_W1  89600         // 7*96 fp32   = 2688
#define SM_BW  92288         // 96 (b2,W3) pairs = 768
#define SM_PAT 93056         // 128 float4
#define SM_IL  95104         // 128 int4
#define SM_TOTAL 97152

__device__ __forceinline__ uint32_t smem_u32(const void* p) {
    uint32_t a;
    asm("{ .reg .u64 t; cvta.to.shared.u64 t, %1; cvt.u32.u64 %0, t; }"
        : "=r"(a) : "l"(p));
    return a;
}
__device__ __forceinline__ void ldsm_x4(uint32_t& r0, uint32_t& r1,
                                        uint32_t& r2, uint32_t& r3, uint32_t a) {
    asm volatile("ldmatrix.sync.aligned.m8n8.x4.shared.b16 {%0,%1,%2,%3}, [%4];"
                 : "=r"(r0), "=r"(r1), "=r"(r2), "=r"(r3) : "r"(a));
}
__device__ __forceinline__ void mma_tf32(float* c, uint32_t a0, uint32_t a1,
                                         uint32_t a2, uint32_t a3,
                                         uint32_t b0, uint32_t b1) {
    asm volatile(
        "mma.sync.aligned.m16n8k8.row.col.f32.tf32.tf32.f32 "
        "{%0,%1,%2,%3}, {%4,%5,%6,%7}, {%8,%9}, {%0,%1,%2,%3};"
        : "+f"(c[0]), "+f"(c[1]), "+f"(c[2]), "+f"(c[3])
        : "r"(a0), "r"(a1), "r"(a2), "r"(a3), "r"(b0), "r"(b1));
}
__device__ __forceinline__ uint32_t to_tf32(float x) {
    uint32_t r;
    asm("cvt.rna.tf32.f32 %0, %1;" : "=r"(r) : "r"(__float_as_uint(x)));
    return r;
}
__device__ __forceinline__ unsigned long long pack2(float x, float y) {
    unsigned long long r;
    asm("mov.b64 %0, {%1, %2};" : "=l"(r) : "f"(x), "f"(y));
    return r;
}
__device__ __forceinline__ void unpack2(unsigned long long v, float& x, float& y) {
    asm("mov.b64 {%0, %1}, %2;" : "=f"(x), "=f"(y) : "l"(v));
}
__device__ __forceinline__ void ffma2(unsigned long long& c, unsigned long long a,
                                      unsigned long long b) {
    asm("fma.rn.f32x2 %0, %1, %2, %0;" : "+l"(c) : "l"(a), "l"(b));
}
__device__ __forceinline__ float elu(float v) {
    return v > 0.f ? v : (__expf(v) - 1.f);
}

// ---------------- merged prep kernel (c1 + tf32 W2^T image) -------------
__global__ void prep_kernel(const float* __restrict__ controls,
                            const float* __restrict__ W1,
                            const float* __restrict__ b1,
                            const int* __restrict__ control_list,
                            const float* __restrict__ W2) {
    int n = blockIdx.x;       // 1024
    int j = threadIdx.x;      // 96
    float v = 0.f;
    if (j < HID) {
        v = b1[j];
#pragma unroll
        for (int kk = 0; kk < 3; kk++) {
            int e = control_list[n * 3 + kk];
            v = fmaf(controls[n * 3 + kk], W1[e * HID + j], v);
        }
    }
    c1g[n * HP + j] = v;
    if (n < HP) {
        // Bimg[n][k=j] = tf32(W2[j][n]); zero-padded
        float w = (n < HID && j < HID) ? W2[j * HID + n] : 0.f;
        Bimg[n * 100 + j] = __uint_as_float(to_tf32(w));
        if (j >= 92) Bimg[n * 100 + j + 4] = 0.f;   // pad cols 96..99 (unused)
    }
}

// ---------------- main kernel ----------------
__global__ void __launch_bounds__(TPB, 2)
lrf_main_kernel(const float* __restrict__ x,
                const float* __restrict__ W1,
                const float* __restrict__ b2,
                const float* __restrict__ W3,
                const float* __restrict__ b3,
                const int* __restrict__ inputs_list,
                float* __restrict__ out) {
    extern __shared__ char sm[];
    const uint32_t smb = smem_u32(sm);
    const int tid = threadIdx.x;
    const int wid = tid >> 5, lid = tid & 31;
    const int b  = blockIdx.x >> 3;
    const int n0 = (blockIdx.x & 7) * ROWS;

    // ---- stage B (38400 B) ----
    {
        const uint4* src = (const uint4*)Bimg;
        uint4* dst = (uint4*)(sm + SM_B);
        for (int i = tid; i < 38400 / 16; i += TPB) dst[i] = src[i];
    }
    // ---- stage W1 (zero-pad cols), fused [b2,W3] pairs ----
    for (int idx = tid; idx < 7 * HP; idx += TPB) {
        int e = idx / HP, j = idx - e * HP;
        ((float*)(sm + SM_W1))[idx] = (j < HID) ? W1[e * HID + j] : 0.f;
    }
    if (tid < HP) {
        float bb = (tid < HID) ? b2[tid] : 0.f;
        float ww = (tid < HID) ? W3[tid] : 0.f;
        ((float*)(sm + SM_BW))[tid * 2]     = bb;
        ((float*)(sm + SM_BW))[tid * 2 + 1] = ww;
    }
    // ---- stage patches + electrode indices ----
    if (tid < ROWS) {
        int n = n0 + tid;
        int pw = n & 31, ph = n >> 5;
        const float* xb = x + (size_t)b * 4096 + ph * 128 + pw * 2;
        float2 r0 = *reinterpret_cast<const float2*>(xb);
        float2 r1 = *reinterpret_cast<const float2*>(xb + 64);
        *reinterpret_cast<float4*>(sm + SM_PAT + tid * 16) =
            make_float4(r0.x, r0.y, r1.x, r1.y);
        *reinterpret_cast<int4*>(sm + SM_IL + tid * 16) =
            *reinterpret_cast<const int4*>(inputs_list + n * 4);
    }
    __syncthreads();

    // ---- phase 1: h1 = elu(c1 + patch·W1rows), tf32-rounded, into A ----
    const float* W1s = (const float*)(sm + SM_W1);
#pragma unroll
    for (int it = 0; it < 6; it++) {
        int item = it * TPB + tid;          // 128 rows x 12 col-groups
        int r = item / 12, jg = item - r * 12;
        int j0 = jg * 8;
        float4 pv = *reinterpret_cast<float4*>(sm + SM_PAT + r * 16);
        int4 ii = *reinterpret_cast<int4*>(sm + SM_IL + r * 16);
        const float* c1p = c1g + (n0 + r) * HP + j0;
        float4 cA = *reinterpret_cast<const float4*>(c1p);
        float4 cB = *reinterpret_cast<const float4*>(c1p + 4);
        unsigned long long a0 = pack2(cA.x, cA.y), a1 = pack2(cA.z, cA.w);
        unsigned long long a2 = pack2(cB.x, cB.y), a3 = pack2(cB.z, cB.w);
#define EACC(EIDX, P) { \
        const float4* wr = (const float4*)(W1s + (EIDX) * HP + j0); \
        float4 w0 = wr[0], w1 = wr[1]; \
        unsigned long long pp = pack2((P), (P)); \
        ffma2(a0, pp, pack2(w0.x, w0.y)); \
        ffma2(a1, pp, pack2(w0.z, w0.w)); \
        ffma2(a2, pp, pack2(w1.x, w1.y)); \
        ffma2(a3, pp, pack2(w1.z, w1.w)); }
        EACC(ii.x, pv.x) EACC(ii.y, pv.y) EACC(ii.z, pv.z) EACC(ii.w, pv.w)
#undef EACC
        float v[8];
        unpack2(a0, v[0], v[1]); unpack2(a1, v[2], v[3]);
        unpack2(a2, v[4], v[5]); unpack2(a3, v[6], v[7]);
        uint32_t t[8];
#pragma unroll
        for (int q = 0; q < 8; q++) t[q] = to_tf32(elu(v[q]));
        char* dst = sm + SM_A + (uint32_t)r * RS + (uint32_t)j0 * 4;
        *reinterpret_cast<uint4*>(dst)      = make_uint4(t[0], t[1], t[2], t[3]);
        *reinterpret_cast<uint4*>(dst + 16) = make_uint4(t[4], t[5], t[6], t[7]);
    }
    __syncthreads();

    // ---- phase 2: warp = m16 x n96, single-pass tf32 ----
    float acc[12][4];
#pragma unroll
    for (int nt = 0; nt < 12; nt++)
#pragma unroll
        for (int q = 0; q < 4; q++) acc[nt][q] = 0.f;

    const uint32_t aBase = smb + SM_A
        + (uint32_t)(wid * 16 + (lid & 7) + ((lid >> 3) & 1) * 8) * RS
        + (uint32_t)(lid >> 4) * 16;
    const uint32_t bBase = smb + SM_B
        + (uint32_t)(lid & 7) * RS + (uint32_t)(lid >> 3) * 16;

#pragma unroll
    for (int jj = 0; jj < 6; jj++) {
        uint32_t a0, a1, a2, a3, a4, a5, a6, a7;
        ldsm_x4(a0, a1, a2, a3, aBase + jj * 64);        // k-step 2jj
        ldsm_x4(a4, a5, a6, a7, aBase + jj * 64 + 32);   // k-step 2jj+1
#pragma unroll
        for (int nt = 0; nt < 12; nt++) {
            uint32_t b0, b1, b2r, b3r;
            ldsm_x4(b0, b1, b2r, b3r, bBase + (uint32_t)nt * 8 * RS + jj * 64);
            mma_tf32(acc[nt], a0, a1, a2, a3, b0,  b1);
            mma_tf32(acc[nt], a4, a5, a6, a7, b2r, b3r);
        }
    }

    // ---- phase 3: out = elu(C + b2) · W3 + b3, shfl over the 4 col lanes ----
    const float b3v = b3[0];
    float part0 = 0.f, part1 = 0.f;
    const char* bwp = sm + SM_BW + (size_t)(lid & 3) * 16;
#pragma unroll
    for (int nt = 0; nt < 12; nt++) {
        float4 bw = *reinterpret_cast<const float4*>(bwp + nt * 64);
        part0 = fmaf(elu(acc[nt][0] + bw.x), bw.y, part0);
        part0 = fmaf(elu(acc[nt][1] + bw.z), bw.w, part0);
        part1 = fmaf(elu(acc[nt][2] + bw.x), bw.y, part1);
        part1 = fmaf(elu(acc[nt][3] + bw.z), bw.w, part1);
    }
#pragma unroll
    for (int off = 1; off < 4; off <<= 1) {
        part0 += __shfl_xor_sync(0xffffffffu, part0, off);
        part1 += __shfl_xor_sync(0xffffffffu, part1, off);
    }
    if ((lid & 3) == 0) {
        int g = n0 + wid * 16 + (lid >> 2);
        out[(size_t)b * NNODES + g]     = part0 + b3v;
        out[(size_t)b * NNODES + g + 8] = part1 + b3v;
    }
}

extern "C" void kernel_launch(void* const* d_in, const int* in_sizes, int n_in,
                              void* d_out, int out_size) {
    const float* x            = (const float*)d_in[0];
    const float* controls     = (const float*)d_in[1];
    const float* W1           = (const float*)d_in[2];
    const float* b1           = (const float*)d_in[3];
    const float* W2           = (const float*)d_in[4];
    const float* b2           = (const float*)d_in[5];
    const float* W3           = (const float*)d_in[6];
    const float* b3           = (const float*)d_in[7];
    const int*   inputs_list  = (const int*)d_in[8];
    const int*   control_list = (const int*)d_in[9];
    float* out = (float*)d_out;

    cudaFuncSetAttribute(lrf_main_kernel,
                         cudaFuncAttributeMaxDynamicSharedMemorySize, SM_TOTAL);

    prep_kernel<<<NNODES, HP>>>(controls, W1, b1, control_list, W2);
    lrf_main_kernel<<<BATCH * (NNODES / ROWS), TPB, SM_TOTAL>>>(
        x, W1, b2, W3, b3, inputs_list, out);
}

// round 7
// speedup vs baseline: 1.4199x; 1.1959x over previous
#include <cuda_runtime.h>
#include <cuda_bf16.h>
#include <cstdint>

#define HID 90
#define HP 96
#define NNODES 1024
#define BATCH 1024
#define TPB 256
#define ROWS 128
#define RS 400               // A-tile row stride (bytes) — conflict-free ldmatrix
#define ES 48                // E / W1B row stride (bytes) — conflict-free ldmatrix

// ---------------- device globals (no allocation allowed) ----------------
__device__ float c1g[NNODES * HP];                   // per-node layer-1 bias
__device__ __align__(16) float Bimg[96 * 100];       // W2^T, tf32-rounded
__device__ __align__(16) float W1Bimg[96 * 12];      // W1^T, tf32, k-padded to 8(+4)

// ---------------- smem layout ----------------
#define SM_A    0            // 128 x 400 = 51200
#define SM_B    51200        // 96 x 400  = 38400
#define SM_W1B  89600        // 96 x 48   = 4608
#define SM_E    94208        // 128 x 48  = 6144  (reused as PART in phase 3)
#define SM_BW   100352       // 96 (b2,W3) pairs = 768
#define SM_TOTAL 101376

__device__ __forceinline__ uint32_t smem_u32(const void* p) {
    uint32_t a;
    asm("{ .reg .u64 t; cvta.to.shared.u64 t, %1; cvt.u32.u64 %0, t; }"
        : "=r"(a) : "l"(p));
    return a;
}
__device__ __forceinline__ void ldsm_x4(uint32_t& r0, uint32_t& r1,
                                        uint32_t& r2, uint32_t& r3, uint32_t a) {
    asm volatile("ldmatrix.sync.aligned.m8n8.x4.shared.b16 {%0,%1,%2,%3}, [%4];"
                 : "=r"(r0), "=r"(r1), "=r"(r2), "=r"(r3) : "r"(a));
}
__device__ __forceinline__ void mma_tf32(float* c, uint32_t a0, uint32_t a1,
                                         uint32_t a2, uint32_t a3,
                                         uint32_t b0, uint32_t b1) {
    asm volatile(
        "mma.sync.aligned.m16n8k8.row.col.f32.tf32.tf32.f32 "
        "{%0,%1,%2,%3}, {%4,%5,%6,%7}, {%8,%9}, {%0,%1,%2,%3};"
        : "+f"(c[0]), "+f"(c[1]), "+f"(c[2]), "+f"(c[3])
        : "r"(a0), "r"(a1), "r"(a2), "r"(a3), "r"(b0), "r"(b1));
}
__device__ __forceinline__ uint32_t to_tf32(float x) {
    uint32_t r;
    asm("cvt.rna.tf32.f32 %0, %1;" : "=r"(r) : "r"(__float_as_uint(x)));
    return r;
}
__device__ __forceinline__ float elu(float v) {
    return v > 0.f ? v : (__expf(v) - 1.f);
}

// ---------------- prep kernel (c1 + tf32 W2^T + tf32 W1^T images) --------
__global__ void prep_kernel(const float* __restrict__ controls,
                            const float* __restrict__ W1,
                            const float* __restrict__ b1,
                            const int* __restrict__ control_list,
                            const float* __restrict__ W2) {
    int n = blockIdx.x;       // 1024
    int j = threadIdx.x;      // 96
    float v = 0.f;
    if (j < HID) {
        v = b1[j];
#pragma unroll
        for (int kk = 0; kk < 3; kk++) {
            int e = control_list[n * 3 + kk];
            v = fmaf(controls[n * 3 + kk], W1[e * HID + j], v);
        }
    }
    c1g[n * HP + j] = v;
    if (n < HP) {
        float w = (n < HID && j < HID) ? W2[j * HID + n] : 0.f;
        Bimg[n * 100 + j] = __uint_as_float(to_tf32(w));
        if (j >= 92) Bimg[n * 100 + j + 4] = 0.f;
        if (j < 12) {
            float w1 = (j < 7 && n < HID) ? W1[j * HID + n] : 0.f;
            W1Bimg[n * 12 + j] = __uint_as_float(to_tf32(w1));
        }
    }
}

// ---------------- main kernel ----------------
__global__ void __launch_bounds__(TPB, 2)
lrf_main_kernel(const float* __restrict__ x,
                const float* __restrict__ b2,
                const float* __restrict__ W3,
                const float* __restrict__ b3,
                const int* __restrict__ inputs_list,
                float* __restrict__ out) {
    extern __shared__ char sm[];
    const uint32_t smb = smem_u32(sm);
    const int tid = threadIdx.x;
    const int wid = tid >> 5, lid = tid & 31;
    const int b  = blockIdx.x >> 3;
    const int n0 = (blockIdx.x & 7) * ROWS;
    const int g = lid >> 2, q = lid & 3;

    // ---- stage B (38400 B) + W1B (4608 B = 288 float4, grid-stride!) ----
    {
        const uint4* src = (const uint4*)Bimg;
        uint4* dst = (uint4*)(sm + SM_B);
        for (int i = tid; i < 38400 / 16; i += TPB) dst[i] = src[i];
        for (int i = tid; i < 96 * 12 / 4; i += TPB)
            ((float4*)(sm + SM_W1B))[i] = ((const float4*)W1Bimg)[i];
    }
    // ---- fused [b2,W3] pairs ----
    if (tid >= 128 && tid < 128 + HP) {
        int c = tid - 128;
        float bb = (c < HID) ? b2[c] : 0.f;
        float ww = (c < HID) ? W3[c] : 0.f;
        ((float*)(sm + SM_BW))[c * 2]     = bb;
        ((float*)(sm + SM_BW))[c * 2 + 1] = ww;
    }
    // ---- build E: [128 rows x 8 k] scattered patch values (tf32) ----
    if (tid < ROWS) {
        int n = n0 + tid;
        int pw = n & 31, ph = n >> 5;
        const float* xb = x + (size_t)b * 4096 + ph * 128 + pw * 2;
        float2 r0 = *reinterpret_cast<const float2*>(xb);
        float2 r1 = *reinterpret_cast<const float2*>(xb + 64);
        int4 il = *reinterpret_cast<const int4*>(inputs_list + n * 4);
        float* er = (float*)(sm + SM_E + tid * ES);
        float4 z = make_float4(0.f, 0.f, 0.f, 0.f);
        ((float4*)er)[0] = z; ((float4*)er)[1] = z; ((float4*)er)[2] = z;
        er[il.x] = __uint_as_float(to_tf32(r0.x));
        er[il.y] = __uint_as_float(to_tf32(r0.y));
        er[il.z] = __uint_as_float(to_tf32(r1.x));
        er[il.w] = __uint_as_float(to_tf32(r1.y));
    }
    __syncthreads();

    // ---- phase 1: h1 = elu(E·W1B + c1g), warp = m16 x n96, k8 MMA ----
    {
        float acc1[12][4];
#pragma unroll
        for (int nt = 0; nt < 12; nt++)
#pragma unroll
            for (int c = 0; c < 4; c++) acc1[nt][c] = 0.f;

        uint32_t eAddr = smb + SM_E
            + (uint32_t)(wid * 16 + (lid & 7) + ((lid >> 3) & 1) * 8) * ES
            + (uint32_t)(lid >> 4) * 16;
        uint32_t a0, a1, a2, a3;
        ldsm_x4(a0, a1, a2, a3, eAddr);

        uint32_t wAddr = smb + SM_W1B
            + (uint32_t)((lid & 7) + (lid >> 4) * 8) * ES
            + (uint32_t)((lid >> 3) & 1) * 16;
#pragma unroll
        for (int nt2 = 0; nt2 < 6; nt2++) {
            uint32_t b0, b1, b2r, b3r;
            ldsm_x4(b0, b1, b2r, b3r, wAddr + (uint32_t)nt2 * 16 * ES);
            mma_tf32(acc1[2 * nt2],     a0, a1, a2, a3, b0,  b1);
            mma_tf32(acc1[2 * nt2 + 1], a0, a1, a2, a3, b2r, b3r);
        }

        // epilogue: + c1g, elu, tf32-round, store A tile
        const float* c1p  = c1g + (size_t)(n0 + wid * 16 + g) * HP;
        const float* c1p8 = c1p + 8 * HP;
        char* aRow0 = sm + SM_A + (uint32_t)(wid * 16 + g) * RS + (uint32_t)q * 8;
        char* aRow8 = aRow0 + 8 * RS;
#pragma unroll
        for (int nt = 0; nt < 12; nt++) {
            float2 ca = *reinterpret_cast<const float2*>(c1p  + nt * 8 + 2 * q);
            float2 cb = *reinterpret_cast<const float2*>(c1p8 + nt * 8 + 2 * q);
            uint2 t0 = make_uint2(to_tf32(elu(acc1[nt][0] + ca.x)),
                                  to_tf32(elu(acc1[nt][1] + ca.y)));
            uint2 t1 = make_uint2(to_tf32(elu(acc1[nt][2] + cb.x)),
                                  to_tf32(elu(acc1[nt][3] + cb.y)));
            *reinterpret_cast<uint2*>(aRow0 + nt * 32) = t0;
            *reinterpret_cast<uint2*>(aRow8 + nt * 32) = t1;
        }
    }
    __syncthreads();

    // ---- phase 2: warp = m32 x n48, single-pass tf32 ----
    const int rowTile = wid >> 1;            // 0..3
    const int nHalf   = wid & 1;             // 0..1
    float acc[2][6][4];
#pragma unroll
    for (int mi = 0; mi < 2; mi++)
#pragma unroll
        for (int ni = 0; ni < 6; ni++)
#pragma unroll
            for (int c = 0; c < 4; c++) acc[mi][ni][c] = 0.f;

    const uint32_t aB = smb + SM_A
        + (uint32_t)(rowTile * 32 + (lid & 7) + ((lid >> 3) & 1) * 8) * RS
        + (uint32_t)(lid >> 4) * 16;
    const uint32_t bB = smb + SM_B
        + (uint32_t)(nHalf * 48 + (lid & 7)) * RS + (uint32_t)(lid >> 3) * 16;

#pragma unroll
    for (int jj = 0; jj < 6; jj++) {
        uint32_t a[2][8];
#pragma unroll
        for (int mi = 0; mi < 2; mi++) {
            uint32_t base = aB + (uint32_t)mi * 16 * RS + jj * 64;
            ldsm_x4(a[mi][0], a[mi][1], a[mi][2], a[mi][3], base);
            ldsm_x4(a[mi][4], a[mi][5], a[mi][6], a[mi][7], base + 32);
        }
#pragma unroll
        for (int ni = 0; ni < 6; ni++) {
            uint32_t b0, b1, b2r, b3r;
            ldsm_x4(b0, b1, b2r, b3r, bB + (uint32_t)ni * 8 * RS + jj * 64);
#pragma unroll
            for (int mi = 0; mi < 2; mi++) {
                mma_tf32(acc[mi][ni], a[mi][0], a[mi][1], a[mi][2], a[mi][3], b0,  b1);
                mma_tf32(acc[mi][ni], a[mi][4], a[mi][5], a[mi][6], a[mi][7], b2r, b3r);
            }
        }
    }

    // ---- phase 3: out = elu(C + b2) · W3 + b3 ----
    float p[2][2] = {{0.f, 0.f}, {0.f, 0.f}};
    const char* bwp = sm + SM_BW + (size_t)nHalf * 384 + (size_t)q * 16;
#pragma unroll
    for (int ni = 0; ni < 6; ni++) {
        float4 bw = *reinterpret_cast<const float4*>(bwp + ni * 64);
#pragma unroll
        for (int mi = 0; mi < 2; mi++) {
            p[mi][0] = fmaf(elu(acc[mi][ni][0] + bw.x), bw.y, p[mi][0]);
            p[mi][0] = fmaf(elu(acc[mi][ni][1] + bw.z), bw.w, p[mi][0]);
            p[mi][1] = fmaf(elu(acc[mi][ni][2] + bw.x), bw.y, p[mi][1]);
            p[mi][1] = fmaf(elu(acc[mi][ni][3] + bw.z), bw.w, p[mi][1]);
        }
    }
#pragma unroll
    for (int off = 1; off < 4; off <<= 1) {
        p[0][0] += __shfl_xor_sync(0xffffffffu, p[0][0], off);
        p[0][1] += __shfl_xor_sync(0xffffffffu, p[0][1], off);
        p[1][0] += __shfl_xor_sync(0xffffffffu, p[1][0], off);
        p[1][1] += __shfl_xor_sync(0xffffffffu, p[1][1], off);
    }
    __syncthreads();                         // E region becomes PART buffer
    float* PART = (float*)(sm + SM_E);
    if (q == 0) {
        int r = rowTile * 32 + g;
        PART[nHalf * 128 + r]      = p[0][0];
        PART[nHalf * 128 + r + 8]  = p[0][1];
        PART[nHalf * 128 + r + 16] = p[1][0];
        PART[nHalf * 128 + r + 24] = p[1][1];
    }
    __syncthreads();
    if (tid < ROWS)
        out[(size_t)b * NNODES + n0 + tid] = PART[tid] + PART[128 + tid] + b3[0];
}

extern "C" void kernel_launch(void* const* d_in, const int* in_sizes, int n_in,
                              void* d_out, int out_size) {
    const float* x            = (const float*)d_in[0];
    const float* controls     = (const float*)d_in[1];
    const float* W1           = (const float*)d_in[2];
    const float* b1           = (const float*)d_in[3];
    const float* W2           = (const float*)d_in[4];
    const float* b2           = (const float*)d_in[5];
    const float* W3           = (const float*)d_in[6];
    const float* b3           = (const float*)d_in[7];
    const int*   inputs_list  = (const int*)d_in[8];
    const int*   control_list = (const int*)d_in[9];
    float* out = (float*)d_out;

    cudaFuncSetAttribute(lrf_main_kernel,
                         cudaFuncAttributeMaxDynamicSharedMemorySize, SM_TOTAL);

    prep_kernel<<<NNODES, HP>>>(controls, W1, b1, control_list, W2);
    lrf_main_kernel<<<BATCH * (NNODES / ROWS), TPB, SM_TOTAL>>>(
        x, b2, W3, b3, inputs_list, out);
}

// round 8
// speedup vs baseline: 1.9163x; 1.3496x over previous
#include <cuda_runtime.h>
#include <cuda_bf16.h>
#include <cstdint>

#define HID 90
#define HP 96
#define NNODES 1024
#define BATCH 1024
#define TPB 256
#define ROWS 128
#define RS 400               // A/B tile row stride (bytes) — conflict-free ldmatrix
#define ES2 80               // E / W1B row stride (bytes, k=16+pad) — conflict-free

// ---------------- device globals (no allocation allowed) ----------------
__device__ __align__(16) float Bimg[96 * 100];       // W2^T, tf32-rounded
__device__ __align__(16) float W1Bimg[96 * 20];      // [W1 | b1 | W1(dup) | b1_lo]

// ---------------- smem layout ----------------
#define SM_A    0            // 128 x 400 = 51200
#define SM_B    51200        // 96 x 400  = 38400  -> 89600
#define SM_W1B  89600        // 96 x 80   = 7680   -> 97280
#define SM_E    97280        // 128 x 80  = 10240  -> 107520 (PART reuse)
#define SM_BW   107520       // 96 (b2,W3) pairs = 768
#define SM_TOTAL 108288

__device__ __forceinline__ uint32_t smem_u32(const void* p) {
    uint32_t a;
    asm("{ .reg .u64 t; cvta.to.shared.u64 t, %1; cvt.u32.u64 %0, t; }"
        : "=r"(a) : "l"(p));
    return a;
}
__device__ __forceinline__ void ldsm_x4(uint32_t& r0, uint32_t& r1,
                                        uint32_t& r2, uint32_t& r3, uint32_t a) {
    asm volatile("ldmatrix.sync.aligned.m8n8.x4.shared.b16 {%0,%1,%2,%3}, [%4];"
                 : "=r"(r0), "=r"(r1), "=r"(r2), "=r"(r3) : "r"(a));
}
__device__ __forceinline__ void mma_tf32(float* c, uint32_t a0, uint32_t a1,
                                         uint32_t a2, uint32_t a3,
                                         uint32_t b0, uint32_t b1) {
    asm volatile(
        "mma.sync.aligned.m16n8k8.row.col.f32.tf32.tf32.f32 "
        "{%0,%1,%2,%3}, {%4,%5,%6,%7}, {%8,%9}, {%0,%1,%2,%3};"
        : "+f"(c[0]), "+f"(c[1]), "+f"(c[2]), "+f"(c[3])
        : "r"(a0), "r"(a1), "r"(a2), "r"(a3), "r"(b0), "r"(b1));
}
__device__ __forceinline__ uint32_t to_tf32(float x) {
    uint32_t r;
    asm("cvt.rna.tf32.f32 %0, %1;" : "=r"(r) : "r"(__float_as_uint(x)));
    return r;
}
__device__ __forceinline__ float elu(float v) {
    return v > 0.f ? v : (__expf(v) - 1.f);
}

// ---------------- prep kernel: tf32 images of W2^T and [W1|b1|W1|b1_lo] ----
__global__ void prep_kernel(const float* __restrict__ W1,
                            const float* __restrict__ b1,
                            const float* __restrict__ W2) {
    int n = blockIdx.x;       // 0..95 (output unit)
    int j = threadIdx.x;      // 0..127
    if (j < 100) {
        float w = (n < HID && j < HID) ? W2[j * HID + n] : 0.f;
        Bimg[n * 100 + j] = __uint_as_float(to_tf32(w));
    }
    if (j < 20) {
        float v = 0.f;
        if (n < HID) {
            if (j < 7)        v = W1[j * HID + n];
            else if (j == 7)  v = b1[n];
            else if (j < 15)  v = W1[(j - 8) * HID + n];
            else if (j == 15) {
                float bb = b1[n];
                v = bb - __uint_as_float(to_tf32(bb));
            }
        }
        W1Bimg[n * 20 + j] = __uint_as_float(to_tf32(v));
    }
}

// ---------------- main kernel: 2 batch images per CTA ----------------
__global__ void __launch_bounds__(TPB, 2)
lrf_main_kernel(const float* __restrict__ x,
                const float* __restrict__ controls,
                const float* __restrict__ b2,
                const float* __restrict__ W3,
                const float* __restrict__ b3,
                const int* __restrict__ inputs_list,
                const int* __restrict__ control_list,
                float* __restrict__ out) {
    extern __shared__ char sm[];
    const uint32_t smb = smem_u32(sm);
    const int tid = threadIdx.x;
    const int wid = tid >> 5, lid = tid & 31;
    const int bpair = (blockIdx.x >> 3) * 2;
    const int n0 = (blockIdx.x & 7) * ROWS;
    const int g = lid >> 2, q = lid & 3;

    // ---- one-time staging ----
    {
        const uint4* src = (const uint4*)Bimg;
        uint4* dst = (uint4*)(sm + SM_B);
        for (int i = tid; i < 38400 / 16; i += TPB) dst[i] = src[i];
        for (int i = tid; i < 96 * 20 / 4; i += TPB)
            ((float4*)(sm + SM_W1B))[i] = ((const float4*)W1Bimg)[i];
    }
    if (tid >= 128 && tid < 128 + HP) {
        int c = tid - 128;
        float bb = (c < HID) ? b2[c] : 0.f;
        float ww = (c < HID) ? W3[c] : 0.f;
        ((float*)(sm + SM_BW))[c * 2]     = bb;
        ((float*)(sm + SM_BW))[c * 2 + 1] = ww;
    }

    // node-dependent (b-independent) values, kept in registers
    int4 il; int cl0 = 0, cl1 = 0, cl2 = 0;
    float cv0 = 0.f, cv1 = 0.f, cv2 = 0.f;
    int pw = 0, ph = 0;
    if (tid < ROWS) {
        int n = n0 + tid;
        pw = n & 31; ph = n >> 5;
        il = *reinterpret_cast<const int4*>(inputs_list + n * 4);
        cl0 = control_list[n * 3];     cl1 = control_list[n * 3 + 1];
        cl2 = control_list[n * 3 + 2];
        cv0 = controls[n * 3];         cv1 = controls[n * 3 + 1];
        cv2 = controls[n * 3 + 2];
    }

    // ldmatrix addresses (b-invariant)
    const uint32_t eAddr = smb + SM_E
        + (uint32_t)(wid * 16 + (lid & 7) + ((lid >> 3) & 1) * 8) * ES2
        + (uint32_t)(lid >> 4) * 16;
    const uint32_t wAddr = smb + SM_W1B
        + (uint32_t)((lid & 7) + (lid >> 4) * 8) * ES2
        + (uint32_t)((lid >> 3) & 1) * 16;
    const int rowTile = wid >> 1, nHalf = wid & 1;
    const uint32_t aB = smb + SM_A
        + (uint32_t)(rowTile * 32 + (lid & 7) + ((lid >> 3) & 1) * 8) * RS
        + (uint32_t)(lid >> 4) * 16;
    const uint32_t bB = smb + SM_B
        + (uint32_t)(nHalf * 48 + (lid & 7)) * RS + (uint32_t)(lid >> 3) * 16;

    for (int r2 = 0; r2 < 2; r2++) {
        const int b = bpair + r2;
        __syncthreads();   // staging done (r0) / prior-round PART reads done (r1)

        // ---- build E: [128 x 16] hi|lo electrode vectors, bias columns ----
        if (tid < ROWS) {
            const float* xb = x + (size_t)b * 4096 + ph * 128 + pw * 2;
            float2 r0v = *reinterpret_cast<const float2*>(xb);
            float2 r1v = *reinterpret_cast<const float2*>(xb + 64);
            float* er = (float*)(sm + SM_E + tid * ES2);
            float4 z = make_float4(0.f, 0.f, 0.f, 0.f);
            ((float4*)er)[0] = z; ((float4*)er)[1] = z;
            ((float4*)er)[2] = z; ((float4*)er)[3] = z; ((float4*)er)[4] = z;
#define PUT(SLOT, V) { float _v = (V); \
            float _h = __uint_as_float(to_tf32(_v)); \
            er[(SLOT)] = _h; \
            er[8 + (SLOT)] = __uint_as_float(to_tf32(_v - _h)); }
            PUT(il.x, r0v.x) PUT(il.y, r0v.y) PUT(il.z, r1v.x) PUT(il.w, r1v.y)
            PUT(cl0, cv0)    PUT(cl1, cv1)    PUT(cl2, cv2)
#undef PUT
            er[7] = 1.0f; er[15] = 1.0f;
        }
        __syncthreads();

        // ---- phase 1: h1 = elu(E·W1B), warp = m16 x n96, k16 (2 steps) ----
        {
            float acc1[12][4];
#pragma unroll
            for (int nt = 0; nt < 12; nt++)
#pragma unroll
                for (int c = 0; c < 4; c++) acc1[nt][c] = 0.f;

            uint32_t a0, a1, a2, a3, a4, a5, a6, a7;
            ldsm_x4(a0, a1, a2, a3, eAddr);
            ldsm_x4(a4, a5, a6, a7, eAddr + 32);
#pragma unroll
            for (int nt2 = 0; nt2 < 6; nt2++) {
                uint32_t b0, b1, b2r, b3r;
                ldsm_x4(b0, b1, b2r, b3r, wAddr + (uint32_t)nt2 * 16 * ES2);
                mma_tf32(acc1[2 * nt2],     a0, a1, a2, a3, b0,  b1);
                mma_tf32(acc1[2 * nt2 + 1], a0, a1, a2, a3, b2r, b3r);
                uint32_t c0, c1, c2r, c3r;
                ldsm_x4(c0, c1, c2r, c3r, wAddr + (uint32_t)nt2 * 16 * ES2 + 32);
                mma_tf32(acc1[2 * nt2],     a4, a5, a6, a7, c0,  c1);
                mma_tf32(acc1[2 * nt2 + 1], a4, a5, a6, a7, c2r, c3r);
            }

            // epilogue: elu, tf32-round, store A tile (no global loads)
            char* aRow0 = sm + SM_A + (uint32_t)(wid * 16 + g) * RS + (uint32_t)q * 8;
            char* aRow8 = aRow0 + 8 * RS;
#pragma unroll
            for (int nt = 0; nt < 12; nt++) {
                uint2 t0 = make_uint2(to_tf32(elu(acc1[nt][0])),
                                      to_tf32(elu(acc1[nt][1])));
                uint2 t1 = make_uint2(to_tf32(elu(acc1[nt][2])),
                                      to_tf32(elu(acc1[nt][3])));
                *reinterpret_cast<uint2*>(aRow0 + nt * 32) = t0;
                *reinterpret_cast<uint2*>(aRow8 + nt * 32) = t1;
            }
        }
        __syncthreads();

        // ---- phase 2: warp = m32 x n48, single-pass tf32 ----
        float acc[2][6][4];
#pragma unroll
        for (int mi = 0; mi < 2; mi++)
#pragma unroll
            for (int ni = 0; ni < 6; ni++)
#pragma unroll
                for (int c = 0; c < 4; c++) acc[mi][ni][c] = 0.f;

#pragma unroll
        for (int jj = 0; jj < 6; jj++) {
            uint32_t a[2][8];
#pragma unroll
            for (int mi = 0; mi < 2; mi++) {
                uint32_t base = aB + (uint32_t)mi * 16 * RS + jj * 64;
                ldsm_x4(a[mi][0], a[mi][1], a[mi][2], a[mi][3], base);
                ldsm_x4(a[mi][4], a[mi][5], a[mi][6], a[mi][7], base + 32);
            }
#pragma unroll
            for (int ni = 0; ni < 6; ni++) {
                uint32_t b0, b1, b2r, b3r;
                ldsm_x4(b0, b1, b2r, b3r, bB + (uint32_t)ni * 8 * RS + jj * 64);
#pragma unroll
                for (int mi = 0; mi < 2; mi++) {
                    mma_tf32(acc[mi][ni], a[mi][0], a[mi][1], a[mi][2], a[mi][3], b0,  b1);
                    mma_tf32(acc[mi][ni], a[mi][4], a[mi][5], a[mi][6], a[mi][7], b2r, b3r);
                }
            }
        }

        // ---- phase 3: out = elu(C + b2) · W3 + b3 ----
        float p[2][2] = {{0.f, 0.f}, {0.f, 0.f}};
        const char* bwp = sm + SM_BW + (size_t)nHalf * 384 + (size_t)q * 16;
#pragma unroll
        for (int ni = 0; ni < 6; ni++) {
            float4 bw = *reinterpret_cast<const float4*>(bwp + ni * 64);
#pragma unroll
            for (int mi = 0; mi < 2; mi++) {
                p[mi][0] = fmaf(elu(acc[mi][ni][0] + bw.x), bw.y, p[mi][0]);
                p[mi][0] = fmaf(elu(acc[mi][ni][1] + bw.z), bw.w, p[mi][0]);
                p[mi][1] = fmaf(elu(acc[mi][ni][2] + bw.x), bw.y, p[mi][1]);
                p[mi][1] = fmaf(elu(acc[mi][ni][3] + bw.z), bw.w, p[mi][1]);
            }
        }
#pragma unroll
        for (int off = 1; off < 4; off <<= 1) {
            p[0][0] += __shfl_xor_sync(0xffffffffu, p[0][0], off);
            p[0][1] += __shfl_xor_sync(0xffffffffu, p[0][1], off);
            p[1][0] += __shfl_xor_sync(0xffffffffu, p[1][0], off);
            p[1][1] += __shfl_xor_sync(0xffffffffu, p[1][1], off);
        }
        __syncthreads();                     // E region becomes PART buffer
        float* PART = (float*)(sm + SM_E);
        if (q == 0) {
            int r = rowTile * 32 + g;
            PART[nHalf * 128 + r]      = p[0][0];
            PART[nHalf * 128 + r + 8]  = p[0][1];
            PART[nHalf * 128 + r + 16] = p[1][0];
            PART[nHalf * 128 + r + 24] = p[1][1];
        }
        __syncthreads();
        if (tid < ROWS)
            out[(size_t)b * NNODES + n0 + tid] = PART[tid] + PART[128 + tid] + b3[0];
    }
}

extern "C" void kernel_launch(void* const* d_in, const int* in_sizes, int n_in,
                              void* d_out, int out_size) {
    const float* x            = (const float*)d_in[0];
    const float* controls     = (const float*)d_in[1];
    const float* W1           = (const float*)d_in[2];
    const float* b1           = (const float*)d_in[3];
    const float* W2           = (const float*)d_in[4];
    const float* b2           = (const float*)d_in[5];
    const float* W3           = (const float*)d_in[6];
    const float* b3           = (const float*)d_in[7];
    const int*   inputs_list  = (const int*)d_in[8];
    const int*   control_list = (const int*)d_in[9];
    float* out = (float*)d_out;

    cudaFuncSetAttribute(lrf_main_kernel,
                         cudaFuncAttributeMaxDynamicSharedMemorySize, SM_TOTAL);

    prep_kernel<<<96, 128>>>(W1, b1, W2);
    lrf_main_kernel<<<(BATCH / 2) * (NNODES / ROWS), TPB, SM_TOTAL>>>(
        x, controls, b2, W3, b3, inputs_list, control_list, out);
}

// round 10
// speedup vs baseline: 1.9932x; 1.0402x over previous
#include <cuda_runtime.h>
#include <cuda_bf16.h>
#include <cstdint>

#define HID 90
#define HP 96
#define NNODES 1024
#define BATCH 1024
#define TPB 256
#define ROWS 128
#define RS 400               // B tile row stride (bytes) — conflict-free ldmatrix
#define ES2 80               // E / W1B row stride (bytes) — conflict-free

// ---------------- device globals (no allocation allowed) ----------------
__device__ __align__(16) float Bimg[96 * 100];       // W2^T, tf32, k-permuted
__device__ __align__(16) float W1Bimg[96 * 20];      // [W1|b1|W1|b1_lo], logical order

// ---------------- smem layout ----------------
#define SM_B    0            // 96 x 400 = 38400
#define SM_W1B  38400        // 96 x 80  = 7680  -> 46080
#define SM_E    46080        // 128 x 80 = 10240 -> 56320
#define SM_BW   56320        // 96 (b2,W3) pairs = 768
#define SM_TOTAL 57088

__device__ __forceinline__ uint32_t smem_u32(const void* p) {
    uint32_t a;
    asm("{ .reg .u64 t; cvta.to.shared.u64 t, %1; cvt.u32.u64 %0, t; }"
        : "=r"(a) : "l"(p));
    return a;
}
__device__ __forceinline__ void ldsm_x4(uint32_t& r0, uint32_t& r1,
                                        uint32_t& r2, uint32_t& r3, uint32_t a) {
    asm volatile("ldmatrix.sync.aligned.m8n8.x4.shared.b16 {%0,%1,%2,%3}, [%4];"
                 : "=r"(r0), "=r"(r1), "=r"(r2), "=r"(r3) : "r"(a));
}
__device__ __forceinline__ void mma_tf32(float* c, uint32_t a0, uint32_t a1,
                                         uint32_t a2, uint32_t a3,
                                         uint32_t b0, uint32_t b1) {
    asm volatile(
        "mma.sync.aligned.m16n8k8.row.col.f32.tf32.tf32.f32 "
        "{%0,%1,%2,%3}, {%4,%5,%6,%7}, {%8,%9}, {%0,%1,%2,%3};"
        : "+f"(c[0]), "+f"(c[1]), "+f"(c[2]), "+f"(c[3])
        : "r"(a0), "r"(a1), "r"(a2), "r"(a3), "r"(b0), "r"(b1));
}
__device__ __forceinline__ void mma_tf32f(float* c, const float* a,
                                          uint32_t b0, uint32_t b1) {
    mma_tf32(c, __float_as_uint(a[0]), __float_as_uint(a[1]),
                __float_as_uint(a[2]), __float_as_uint(a[3]), b0, b1);
}
__device__ __forceinline__ uint32_t to_tf32(float x) {
    uint32_t r;
    asm("cvt.rna.tf32.f32 %0, %1;" : "=r"(r) : "r"(__float_as_uint(x)));
    return r;
}
__device__ __forceinline__ float elu(float v) {
    return v > 0.f ? v : (__expf(v) - 1.f);
}

// ---------------- prep kernel ----------------
// Bimg k-dim: logical h1 unit c stored at physical position sigma(c) within
// each 8-block, sigma(c) = (c&1)*4 + (c>>1). W1B stays in logical order.
__global__ void prep_kernel(const float* __restrict__ W1,
                            const float* __restrict__ b1,
                            const float* __restrict__ W2) {
    int c = blockIdx.x;       // 0..95 logical h1 unit
    int j = threadIdx.x;      // 0..127
    int p = (c & ~7) | (((c & 1) << 2) | ((c & 7) >> 1));
    if (j < 96) {
        // Bimg[row = layer-2 out unit j][k physical p] = W2[c][j]
        float w = (c < HID && j < HID) ? W2[c * HID + j] : 0.f;
        Bimg[j * 100 + p] = __uint_as_float(to_tf32(w));
    }
    if (j < 20) {
        float v = 0.f;
        if (c < HID) {
            if (j < 7)        v = W1[j * HID + c];
            else if (j == 7)  v = b1[c];
            else if (j < 15)  v = W1[(j - 8) * HID + c];
            else if (j == 15) {
                float bb = b1[c];
                v = bb - __uint_as_float(to_tf32(bb));
            }
        }
        W1Bimg[c * 20 + j] = __uint_as_float(to_tf32(v));   // logical order
    }
}

// ---------------- main kernel: fused 3-layer MLP, 2 images per CTA ------
__global__ void __launch_bounds__(TPB, 3)
lrf_main_kernel(const float* __restrict__ x,
                const float* __restrict__ controls,
                const float* __restrict__ b2,
                const float* __restrict__ W3,
                const float* __restrict__ b3,
                const int* __restrict__ inputs_list,
                const int* __restrict__ control_list,
                float* __restrict__ out) {
    extern __shared__ char sm[];
    const uint32_t smb = smem_u32(sm);
    const int tid = threadIdx.x;
    const int wid = tid >> 5, lid = tid & 31;
    const int bpair = (blockIdx.x >> 3) * 2;
    const int n0 = (blockIdx.x & 7) * ROWS;
    const int g = lid >> 2, q = lid & 3;

    // ---- one-time staging ----
    {
        const uint4* src = (const uint4*)Bimg;
        uint4* dst = (uint4*)(sm + SM_B);
        for (int i = tid; i < 38400 / 16; i += TPB) dst[i] = src[i];
        for (int i = tid; i < 96 * 20 / 4; i += TPB)
            ((float4*)(sm + SM_W1B))[i] = ((const float4*)W1Bimg)[i];
    }
    if (tid >= 128 && tid < 128 + HP) {
        int c = tid - 128;
        float bb = (c < HID) ? b2[c] : 0.f;
        float ww = (c < HID) ? W3[c] : 0.f;
        ((float*)(sm + SM_BW))[c * 2]     = bb;
        ((float*)(sm + SM_BW))[c * 2 + 1] = ww;
    }

    // ldmatrix addresses (b-invariant)
    const uint32_t eAddr = smb + SM_E
        + (uint32_t)(wid * 16 + (lid & 7) + ((lid >> 3) & 1) * 8) * ES2
        + (uint32_t)(lid >> 4) * 16;
    const uint32_t wAddr = smb + SM_W1B
        + (uint32_t)((lid & 7) + (lid >> 4) * 8) * ES2
        + (uint32_t)((lid >> 3) & 1) * 16;
    const uint32_t bB = smb + SM_B
        + (uint32_t)(lid & 7) * RS + (uint32_t)(lid >> 3) * 16;

    for (int r2 = 0; r2 < 2; r2++) {
        const int b = bpair + r2;
        __syncthreads();   // staging done / prior image's E reads done

        // ---- build E: [128 x 16] hi|lo electrode vectors + bias cols ----
        if (tid < ROWS) {
            int n = n0 + tid;
            int pw = n & 31, ph = n >> 5;
            const float* xb = x + (size_t)b * 4096 + ph * 128 + pw * 2;
            float2 r0v = *reinterpret_cast<const float2*>(xb);
            float2 r1v = *reinterpret_cast<const float2*>(xb + 64);
            int4 il = *reinterpret_cast<const int4*>(inputs_list + n * 4);
            int cl0 = control_list[n * 3], cl1 = control_list[n * 3 + 1],
                cl2 = control_list[n * 3 + 2];
            float cv0 = controls[n * 3], cv1 = controls[n * 3 + 1],
                  cv2 = controls[n * 3 + 2];
            float* er = (float*)(sm + SM_E + tid * ES2);
            float4 z = make_float4(0.f, 0.f, 0.f, 0.f);
            ((float4*)er)[0] = z; ((float4*)er)[1] = z;
            ((float4*)er)[2] = z; ((float4*)er)[3] = z; ((float4*)er)[4] = z;
#define PUT(SLOT, V) { float _v = (V); \
            float _h = __uint_as_float(__float_as_uint(_v) & 0xFFFFE000u); \
            er[(SLOT)] = _h; er[8 + (SLOT)] = _v - _h; }
            PUT(il.x, r0v.x) PUT(il.y, r0v.y) PUT(il.z, r1v.x) PUT(il.w, r1v.y)
            PUT(cl0, cv0)    PUT(cl1, cv1)    PUT(cl2, cv2)
#undef PUT
            er[7] = 1.0f; er[15] = 1.0f;
        }
        __syncthreads();

        // ---- phase 1: h1 = elu(E·W1B); C fragments become phase-2 A
        //      fragments directly (Bimg k-permutation makes layouts meet) ----
        float aF[12][4];
        {
            float acc1[12][4];
#pragma unroll
            for (int nt = 0; nt < 12; nt++)
#pragma unroll
                for (int c = 0; c < 4; c++) acc1[nt][c] = 0.f;

            uint32_t a0, a1, a2, a3, a4, a5, a6, a7;
            ldsm_x4(a0, a1, a2, a3, eAddr);
            ldsm_x4(a4, a5, a6, a7, eAddr + 32);
#pragma unroll
            for (int nt2 = 0; nt2 < 6; nt2++) {
                uint32_t b0, b1, b2r, b3r;
                ldsm_x4(b0, b1, b2r, b3r, wAddr + (uint32_t)nt2 * 16 * ES2);
                mma_tf32(acc1[2 * nt2],     a0, a1, a2, a3, b0,  b1);
                mma_tf32(acc1[2 * nt2 + 1], a0, a1, a2, a3, b2r, b3r);
                uint32_t c0, c1, c2r, c3r;
                ldsm_x4(c0, c1, c2r, c3r, wAddr + (uint32_t)nt2 * 16 * ES2 + 32);
                mma_tf32(acc1[2 * nt2],     a4, a5, a6, a7, c0,  c1);
                mma_tf32(acc1[2 * nt2 + 1], a4, a5, a6, a7, c2r, c3r);
            }
            // elu + C->A component reorder {c0,c2,c1,c3}; raw fp32 (HMMA truncates)
#pragma unroll
            for (int nt = 0; nt < 12; nt++) {
                aF[nt][0] = elu(acc1[nt][0]);
                aF[nt][1] = elu(acc1[nt][2]);
                aF[nt][2] = elu(acc1[nt][1]);
                aF[nt][3] = elu(acc1[nt][3]);
            }
        }

        // ---- phase 2+3: warp = m16 x n96 in two n48 halves, A in regs ----
        float p0 = 0.f, p1 = 0.f;
        const char* bwbase = sm + SM_BW + (size_t)q * 16;
#pragma unroll
        for (int h = 0; h < 2; h++) {
            float acc[6][4];
#pragma unroll
            for (int nt = 0; nt < 6; nt++)
#pragma unroll
                for (int c = 0; c < 4; c++) acc[nt][c] = 0.f;

            const uint32_t bRow = bB + (uint32_t)h * 48 * RS;
#pragma unroll
            for (int kh = 0; kh < 6; kh++) {
#pragma unroll
                for (int nt = 0; nt < 6; nt++) {
                    uint32_t b0, b1, b2r, b3r;
                    ldsm_x4(b0, b1, b2r, b3r,
                            bRow + (uint32_t)nt * 8 * RS + kh * 64);
                    mma_tf32f(acc[nt], aF[2 * kh],     b0,  b1);
                    mma_tf32f(acc[nt], aF[2 * kh + 1], b2r, b3r);
                }
            }
#pragma unroll
            for (int nt = 0; nt < 6; nt++) {
                float4 bw = *reinterpret_cast<const float4*>(
                    bwbase + h * 384 + nt * 64);
                p0 = fmaf(elu(acc[nt][0] + bw.x), bw.y, p0);
                p0 = fmaf(elu(acc[nt][1] + bw.z), bw.w, p0);
                p1 = fmaf(elu(acc[nt][2] + bw.x), bw.y, p1);
                p1 = fmaf(elu(acc[nt][3] + bw.z), bw.w, p1);
            }
        }
        p0 += __shfl_xor_sync(0xffffffffu, p0, 1);
        p0 += __shfl_xor_sync(0xffffffffu, p0, 2);
        p1 += __shfl_xor_sync(0xffffffffu, p1, 1);
        p1 += __shfl_xor_sync(0xffffffffu, p1, 2);
        if (q == 0) {
            float b3v = b3[0];
            int r = n0 + wid * 16 + g;
            out[(size_t)b * NNODES + r]     = p0 + b3v;
            out[(size_t)b * NNODES + r + 8] = p1 + b3v;
        }
    }
}

extern "C" void kernel_launch(void* const* d_in, const int* in_sizes, int n_in,
                              void* d_out, int out_size) {
    const float* x            = (const float*)d_in[0];
    const float* controls     = (const float*)d_in[1];
    const float* W1           = (const float*)d_in[2];
    const float* b1           = (const float*)d_in[3];
    const float* W2           = (const float*)d_in[4];
    const float* b2           = (const float*)d_in[5];
    const float* W3           = (const float*)d_in[6];
    const float* b3           = (const float*)d_in[7];
    const int*   inputs_list  = (const int*)d_in[8];
    const int*   control_list = (const int*)d_in[9];
    float* out = (float*)d_out;

    cudaFuncSetAttribute(lrf_main_kernel,
                         cudaFuncAttributeMaxDynamicSharedMemorySize, SM_TOTAL);

    prep_kernel<<<96, 128>>>(W1, b1, W2);
    lrf_main_kernel<<<(BATCH / 2) * (NNODES / ROWS), TPB, SM_TOTAL>>>(
        x, controls, b2, W3, b3, inputs_list, control_list, out);
}